// round 8
// baseline (speedup 1.0000x reference)
#include <cuda_runtime.h>
#include <cuda_bf16.h>

#define NN 40000
#define NE 640000
#define ND 128
#define ED 64

typedef unsigned long long u64;

// Scratch (static device allocations — allowed)
// g_AB is PERMUTED: A' cols [0,128): pcol = c0*32 + nt*2 + b  (orig col = nt*8+2c0+b)
//                   B' cols [128,256): 128 + pcol, with b1 folded in.
// g_P is PERMUTED the same way; g_Bgi k-index is permuted to compensate.
__device__ float g_AB[NN * 256];
__device__ float g_P[NN * ND];
__device__ float g_G[NN];
__device__ float g_WtH[ND * 384];
__device__ float g_Wf[ND * 384];
__device__ float g_bf[384];
// Pre-packed bf16-split B fragments for mma.m16n8k16: uint4{bh0,bh1,bl0,bl1}
__device__ uint4 g_Bab[32 * 8 * 32];  // W1 a|b (256 cols), k16=8
__device__ uint4 g_Bgi[48 * 8 * 32];  // Wfold (384 cols), k PERMUTED
__device__ uint4 g_Bgh[48 * 8 * 32];  // WtH   (384 cols)
__device__ uint4 g_Bc [16 * 4 * 32];  // W1c (128 cols, K=64): [nt*4+k16][lane]

// ---- packed f32x2 helpers ----
__device__ __forceinline__ u64 pk(float a, float b) {
    u64 d; asm("mov.b64 %0, {%1,%2};" : "=l"(d)
               : "r"(__float_as_uint(a)), "r"(__float_as_uint(b)));
    return d;
}
__device__ __forceinline__ float2 upk(u64 v) {
    unsigned a, b; asm("mov.b64 {%0,%1}, %2;" : "=r"(a), "=r"(b) : "l"(v));
    return make_float2(__uint_as_float(a), __uint_as_float(b));
}
__device__ __forceinline__ u64 fma2(u64 a, u64 b, u64 c) {
    u64 d; asm("fma.rn.f32x2 %0, %1, %2, %3;" : "=l"(d) : "l"(a), "l"(b), "l"(c));
    return d;
}
__device__ __forceinline__ u64 add2(u64 a, u64 b) {
    u64 d; asm("add.rn.f32x2 %0, %1, %2;" : "=l"(d) : "l"(a), "l"(b));
    return d;
}
__device__ __forceinline__ void red4(float* p, float4 v) {
    asm volatile("red.global.add.v4.f32 [%0], {%1, %2, %3, %4};"
                 :: "l"(p), "f"(v.x), "f"(v.y), "f"(v.z), "f"(v.w) : "memory");
}
__device__ __forceinline__ float fsig(float x) { return 1.f / (1.f + __expf(-x)); }
__device__ __forceinline__ float ftanh(float x) {
    float e = __expf(2.f * fabsf(x));
    return copysignf(1.f - 2.f / (e + 1.f), x);
}

// ---- bf16-split helpers ----
__device__ __forceinline__ unsigned bfpack(float x0, float x1) {
    unsigned r; asm("cvt.rn.bf16x2.f32 %0, %1, %2;" : "=r"(r) : "f"(x1), "f"(x0));
    return r;
}
__device__ __forceinline__ void bfsplit(float x0, float x1, unsigned& h, unsigned& lo) {
    h = bfpack(x0, x1);
    __nv_bfloat162 hb = *(__nv_bfloat162*)&h;
    float l0 = x0 - __bfloat162float(hb.x);
    float l1 = x1 - __bfloat162float(hb.y);
    lo = bfpack(l0, l1);
}
__device__ __forceinline__ void mma16(float* c, const unsigned* a, unsigned b0, unsigned b1) {
    asm("mma.sync.aligned.m16n8k16.row.col.f32.bf16.bf16.f32 "
        "{%0,%1,%2,%3},{%4,%5,%6,%7},{%8,%9},{%0,%1,%2,%3};"
        : "+f"(c[0]), "+f"(c[1]), "+f"(c[2]), "+f"(c[3])
        : "r"(a[0]), "r"(a[1]), "r"(a[2]), "r"(a[3]), "r"(b0), "r"(b1));
}
// permuted col -> original col
#define ORIGCOL(k) ((((k) >> 1) & 15) * 8 + ((k) >> 5) * 2 + ((k) & 1))

__global__ void k_zero() {
    int i = blockIdx.x * blockDim.x + threadIdx.x;
    if (i < NN * ND / 4)
        reinterpret_cast<float4*>(g_P)[i] = make_float4(0.f, 0.f, 0.f, 0.f);
    if (i < NN / 4)
        reinterpret_cast<float4*>(g_G)[i] = make_float4(0.f, 0.f, 0.f, 0.f);
}

__global__ void k_transH(const float* __restrict__ Whh) {
    int idx = blockIdx.x * blockDim.x + threadIdx.x;
    if (idx < 384 * ND) {
        int k = idx / 384, m = idx % 384;
        g_WtH[idx] = Whh[m * ND + k];
    }
}

__global__ void __launch_bounds__(384) k_fold(const float* __restrict__ W2,
                                              const float* __restrict__ Wih,
                                              const float* __restrict__ b2) {
    __shared__ float sw[ND], sb[ND];
    int q = blockIdx.x, m = threadIdx.x;
    if (m < ND) { sw[m] = W2[q * ND + m]; sb[m] = b2[m]; }
    __syncthreads();
    float acc = 0.f, accb = 0.f;
    const float* wr = Wih + m * ND;
    #pragma unroll 4
    for (int k = 0; k < ND; k++) {
        float w = wr[k];
        acc  = fmaf(sw[k], w, acc);
        accb = fmaf(sb[k], w, accb);
    }
    g_Wf[q * 384 + m] = acc;
    if (q == 0) g_bf[m] = accb;
}

// Pack B fragments for all GEMMs. 34816 threads.
__global__ void k_prep(const float* __restrict__ W1) {
    int i = blockIdx.x * 256 + threadIdx.x;
    int lane = i & 31;
    int n8 = lane >> 2, kq = lane & 3;
    unsigned h0, l0, h1, l1;
    if (i < 8192) {                            // g_Bab from W1 rows 0..255
        int k16 = (i >> 5) & 7, nt = i >> 8;
        int nn = nt * 8 + n8, kb = k16 * 16 + 2 * kq;
        const float* base = (nn < 128) ? (W1 + nn) : (W1 + 128 * 128 + nn - 128);
        bfsplit(base[kb * 128], base[(kb + 1) * 128], h0, l0);
        bfsplit(base[(kb + 8) * 128], base[(kb + 9) * 128], h1, l1);
        g_Bab[i] = make_uint4(h0, h1, l0, l1);
    } else if (i < 8192 + 12288) {             // g_Bgi from g_Wf, k PERMUTED
        int ii = i - 8192;
        int k16 = (ii >> 5) & 7, nt = ii >> 8;
        int nn = nt * 8 + n8, kb = k16 * 16 + 2 * kq;
        bfsplit(g_Wf[ORIGCOL(kb) * 384 + nn], g_Wf[ORIGCOL(kb + 1) * 384 + nn], h0, l0);
        bfsplit(g_Wf[ORIGCOL(kb + 8) * 384 + nn], g_Wf[ORIGCOL(kb + 9) * 384 + nn], h1, l1);
        g_Bgi[ii] = make_uint4(h0, h1, l0, l1);
    } else if (i < 8192 + 24576) {             // g_Bgh from g_WtH
        int ii = i - 8192 - 12288;
        int k16 = (ii >> 5) & 7, nt = ii >> 8;
        int nn = nt * 8 + n8, kb = k16 * 16 + 2 * kq;
        bfsplit(g_WtH[kb * 384 + nn], g_WtH[(kb + 1) * 384 + nn], h0, l0);
        bfsplit(g_WtH[(kb + 8) * 384 + nn], g_WtH[(kb + 9) * 384 + nn], h1, l1);
        g_Bgh[ii] = make_uint4(h0, h1, l0, l1);
    } else {                                   // g_Bc from W1 rows 256..319 (K=64)
        int ii = i - 8192 - 24576;             // [0, 2048)
        int idx = ii >> 5;                     // nt*4 + k16
        int k16 = idx & 3, nt = idx >> 2;
        int nn = nt * 8 + n8, kb = k16 * 16 + 2 * kq;
        const float* base = W1 + 256 * 128 + nn;
        bfsplit(base[kb * 128], base[(kb + 1) * 128], h0, l0);
        bfsplit(base[(kb + 8) * 128], base[(kb + 9) * 128], h1, l1);
        g_Bc[ii] = make_uint4(h0, h1, l0, l1);
    }
}

// nodeAB on tensor cores; stores PERMUTED layout, folds b1 into B'.
__global__ void __launch_bounds__(128) k_nodeAB_t(const float* __restrict__ nf,
                                                  const float* __restrict__ b1) {
    __shared__ unsigned sah[32][68], sal[32][68];
    int t = threadIdx.x, l = t & 31, w = t >> 5;
    int base = blockIdx.x * 32;
    for (int i = t; i < 32 * 64; i += 128) {
        int r = i >> 6, pc = i & 63;
        float2 v = *(const float2*)&nf[(base + r) * ND + pc * 2];
        unsigned h, lo; bfsplit(v.x, v.y, h, lo);
        sah[r][pc] = h; sal[r][pc] = lo;
    }
    __syncthreads();
    float acc[2][8][4];
    #pragma unroll
    for (int m = 0; m < 2; m++)
        #pragma unroll
        for (int n = 0; n < 8; n++)
            #pragma unroll
            for (int x = 0; x < 4; x++) acc[m][n][x] = 0.f;
    int r0 = l >> 2, c0 = l & 3;
    #pragma unroll
    for (int k16 = 0; k16 < 8; k16++) {
        unsigned ah[2][4], al[2][4];
        int kp = k16 * 8 + c0;
        #pragma unroll
        for (int m = 0; m < 2; m++) {
            ah[m][0] = sah[m * 16 + r0][kp];     ah[m][1] = sah[m * 16 + r0 + 8][kp];
            ah[m][2] = sah[m * 16 + r0][kp + 4]; ah[m][3] = sah[m * 16 + r0 + 8][kp + 4];
            al[m][0] = sal[m * 16 + r0][kp];     al[m][1] = sal[m * 16 + r0 + 8][kp];
            al[m][2] = sal[m * 16 + r0][kp + 4]; al[m][3] = sal[m * 16 + r0 + 8][kp + 4];
        }
        #pragma unroll
        for (int n = 0; n < 8; n++) {
            uint4 bv = g_Bab[((w * 8 + n) * 8 + k16) * 32 + l];
            #pragma unroll
            for (int m = 0; m < 2; m++) {
                mma16(acc[m][n], ah[m], bv.x, bv.y);
                mma16(acc[m][n], al[m], bv.x, bv.y);
                mma16(acc[m][n], ah[m], bv.z, bv.w);
            }
        }
    }
    #pragma unroll
    for (int m = 0; m < 2; m++)
        #pragma unroll
        for (int n = 0; n < 8; n++) {
            int ntg = w * 8 + n;
            int row = base + m * 16 + r0;
            int nt = ntg & 15;
            int pc = (ntg < 16 ? 0 : 128) + c0 * 32 + nt * 2;
            float2 add = make_float2(0.f, 0.f);
            if (ntg >= 16) add = *(const float2*)&b1[nt * 8 + 2 * c0];
            *(float2*)&g_AB[row * 256 + pc] =
                make_float2(acc[m][n][0] + add.x, acc[m][n][1] + add.y);
            *(float2*)&g_AB[(row + 8) * 256 + pc] =
                make_float2(acc[m][n][2] + add.x, acc[m][n][3] + add.y);
        }
}

// Edge kernel on tensor cores: warp-autonomous, 16 edges/warp-tile.
// Thread l: r0=l>>2 (edge rows r0, r0+8), c0=l&3 (owns permuted cols c0*32..+31).
__global__ void __launch_bounds__(128, 4) k_edge_t(
    const float* __restrict__ ef, const int* __restrict__ ei,
    const float* __restrict__ lng, const float* __restrict__ lnb,
    const float* __restrict__ gw, const float* __restrict__ gb) {
    __shared__ unsigned shi[4][16 * 36], slo[4][16 * 36];
    __shared__ float sg[4][16];
    __shared__ float s_ln[256];   // lng[0..128) | lnb[128..256)
    int t = threadIdx.x, l = t & 31, w = t >> 5;
    s_ln[t] = lng[t];
    s_ln[128 + t] = lnb[t];
    __syncthreads();
    unsigned* myhi = shi[w];
    unsigned* mylo = slo[w];
    int r0 = l >> 2, c0 = l & 3;
    float gb0 = gb[0];

    for (int e0 = (blockIdx.x * 4 + w) * 16; e0 < NE; e0 += gridDim.x * 64) {
        __syncwarp();
        int sv  = ei[e0 + (l & 15)];
        int dvv = ei[NE + e0 + (l & 15)];

        // stage ef bf16-split + gate (fused into same loads). edge e=l>>1, half h=l&1.
        {
            int e = l >> 1, h = l & 1;
            const float4* src4 = (const float4*)(ef + (size_t)(e0 + e) * ED) + h * 8;
            const float4* gw4 = (const float4*)gw + h * 8;
            float gd = 0.f;
            #pragma unroll
            for (int i = 0; i < 8; i++) {
                float4 v = src4[i];
                float4 g4 = gw4[i];
                gd = fmaf(v.x, g4.x, gd); gd = fmaf(v.y, g4.y, gd);
                gd = fmaf(v.z, g4.z, gd); gd = fmaf(v.w, g4.w, gd);
                unsigned h0, l0, h1, l1;
                bfsplit(v.x, v.y, h0, l0);
                bfsplit(v.z, v.w, h1, l1);
                int kp = e * 36 + h * 16 + 2 * i;
                myhi[kp] = h0; myhi[kp + 1] = h1;
                mylo[kp] = l0; mylo[kp + 1] = l1;
            }
            gd += __shfl_xor_sync(0xffffffffu, gd, 1);
            if (h == 0) sg[w][e] = fsig(gd + gb0);
        }

        // base gather: acc[nt][{0,1}]=edge r0, [{2,3}]=edge r0+8 (b1 folded into B')
        float acc[16][4];
        int d0 = __shfl_sync(0xffffffffu, dvv, r0);
        int d1 = __shfl_sync(0xffffffffu, dvv, r0 + 8);
        {
            int s0 = __shfl_sync(0xffffffffu, sv, r0);
            int s1 = __shfl_sync(0xffffffffu, sv, r0 + 8);
            const float4* A0 = (const float4*)(g_AB + (size_t)s0 * 256 + c0 * 32);
            const float4* B0 = (const float4*)(g_AB + (size_t)d0 * 256 + 128 + c0 * 32);
            const float4* A1 = (const float4*)(g_AB + (size_t)s1 * 256 + c0 * 32);
            const float4* B1 = (const float4*)(g_AB + (size_t)d1 * 256 + 128 + c0 * 32);
            #pragma unroll
            for (int i = 0; i < 8; i++) {
                float4 a = A0[i], b = B0[i];
                acc[2 * i][0]     = a.x + b.x; acc[2 * i][1]     = a.y + b.y;
                acc[2 * i + 1][0] = a.z + b.z; acc[2 * i + 1][1] = a.w + b.w;
                float4 a2 = A1[i], b2 = B1[i];
                acc[2 * i][2]     = a2.x + b2.x; acc[2 * i][3]     = a2.y + b2.y;
                acc[2 * i + 1][2] = a2.z + b2.z; acc[2 * i + 1][3] = a2.w + b2.w;
            }
        }
        __syncwarp();

        // h += ef @ W1c on tensor cores (bf16-split, 3 terms)
        #pragma unroll
        for (int k16 = 0; k16 < 4; k16++) {
            unsigned ah[4], al[4];
            int kp = k16 * 8 + c0;
            ah[0] = myhi[r0 * 36 + kp];           ah[1] = myhi[(r0 + 8) * 36 + kp];
            ah[2] = myhi[r0 * 36 + kp + 4];       ah[3] = myhi[(r0 + 8) * 36 + kp + 4];
            al[0] = mylo[r0 * 36 + kp];           al[1] = mylo[(r0 + 8) * 36 + kp];
            al[2] = mylo[r0 * 36 + kp + 4];       al[3] = mylo[(r0 + 8) * 36 + kp + 4];
            #pragma unroll
            for (int nt = 0; nt < 16; nt++) {
                uint4 bv = g_Bc[(nt * 4 + k16) * 32 + l];
                mma16(acc[nt], ah, bv.x, bv.y);
                mma16(acc[nt], al, bv.x, bv.y);
                mma16(acc[nt], ah, bv.z, bv.w);
            }
        }

        // LayerNorm stats: packed (edge0, edge1); reduce across the 4-lane col group
        u64 s = 0, q = 0;
        #pragma unroll
        for (int nt = 0; nt < 16; nt++) {
            u64 v0 = pk(acc[nt][0], acc[nt][2]);
            u64 v1 = pk(acc[nt][1], acc[nt][3]);
            s = add2(s, add2(v0, v1));
            q = fma2(v0, v0, q);
            q = fma2(v1, v1, q);
        }
        s = add2(s, __shfl_xor_sync(0xffffffffu, s, 1));
        s = add2(s, __shfl_xor_sync(0xffffffffu, s, 2));
        q = add2(q, __shfl_xor_sync(0xffffffffu, q, 1));
        q = add2(q, __shfl_xor_sync(0xffffffffu, q, 2));

        float2 sf = upk(s), qf = upk(q);
        float mu0 = sf.x * (1.f / ND), mu1 = sf.y * (1.f / ND);
        float rs0 = rsqrtf(qf.x * (1.f / ND) - mu0 * mu0 + 1e-5f);
        float rs1 = rsqrtf(qf.y * (1.f / ND) - mu1 * mu1 + 1e-5f);
        float g0 = sg[w][r0], g1 = sg[w][r0 + 8];

        // normalize, relu, gate, scatter (permuted g_P; 2 nt per red4)
        #pragma unroll
        for (int i = 0; i < 8; i++) {
            int nt = 2 * i;
            float2 lg_a = *(const float2*)&s_ln[nt * 8 + 2 * c0];
            float2 lb_a = *(const float2*)&s_ln[128 + nt * 8 + 2 * c0];
            float2 lg_b = *(const float2*)&s_ln[(nt + 1) * 8 + 2 * c0];
            float2 lb_b = *(const float2*)&s_ln[128 + (nt + 1) * 8 + 2 * c0];
            float4 o0, o1;
            o0.x = fmaxf((acc[nt][0]     - mu0) * rs0 * lg_a.x + lb_a.x, 0.f) * g0;
            o0.y = fmaxf((acc[nt][1]     - mu0) * rs0 * lg_a.y + lb_a.y, 0.f) * g0;
            o0.z = fmaxf((acc[nt + 1][0] - mu0) * rs0 * lg_b.x + lb_b.x, 0.f) * g0;
            o0.w = fmaxf((acc[nt + 1][1] - mu0) * rs0 * lg_b.y + lb_b.y, 0.f) * g0;
            o1.x = fmaxf((acc[nt][2]     - mu1) * rs1 * lg_a.x + lb_a.x, 0.f) * g1;
            o1.y = fmaxf((acc[nt][3]     - mu1) * rs1 * lg_a.y + lb_a.y, 0.f) * g1;
            o1.z = fmaxf((acc[nt + 1][2] - mu1) * rs1 * lg_b.x + lb_b.x, 0.f) * g1;
            o1.w = fmaxf((acc[nt + 1][3] - mu1) * rs1 * lg_b.y + lb_b.y, 0.f) * g1;
            red4(&g_P[(size_t)d0 * ND + c0 * 32 + nt * 2], o0);
            red4(&g_P[(size_t)d1 * ND + c0 * 32 + nt * 2], o1);
        }
        if (l < 16) atomicAdd(&g_G[dvv], sg[w][l]);
    }
}

// GRU on tensor cores (unchanged; g_Bgi is k-permuted to match permuted g_P).
__global__ void __launch_bounds__(128) k_gru_t(const float* __restrict__ nf,
                                               const float* __restrict__ bih,
                                               const float* __restrict__ bhh,
                                               float* __restrict__ out) {
    __shared__ unsigned sph[16][68], spl[16][68], snh[16][68], snl[16][68];
    __shared__ float snraw[16][132];
    __shared__ float sgi[128][49];
    int t = threadIdx.x, l = t & 31, w = t >> 5;
    int base = blockIdx.x * 16;
    for (int i = t; i < 16 * 64; i += 128) {
        int r = i >> 6, pc = i & 63;
        float2 vp = *(const float2*)&g_P[(base + r) * ND + pc * 2];
        float2 vn = *(const float2*)&nf[(base + r) * ND + pc * 2];
        unsigned h, lo;
        bfsplit(vp.x, vp.y, h, lo); sph[r][pc] = h; spl[r][pc] = lo;
        bfsplit(vn.x, vn.y, h, lo); snh[r][pc] = h; snl[r][pc] = lo;
        snraw[r][pc * 2] = vn.x; snraw[r][pc * 2 + 1] = vn.y;
    }
    __syncthreads();
    int r0 = l >> 2, c0 = l & 3;
    float acc[12][4];

    #pragma unroll
    for (int j = 0; j < 12; j++)
        #pragma unroll
        for (int x = 0; x < 4; x++) acc[j][x] = 0.f;
    #pragma unroll
    for (int k16 = 0; k16 < 8; k16++) {
        unsigned ah[4], al[4];
        int kp = k16 * 8 + c0;
        ah[0] = sph[r0][kp];     ah[1] = sph[r0 + 8][kp];
        ah[2] = sph[r0][kp + 4]; ah[3] = sph[r0 + 8][kp + 4];
        al[0] = spl[r0][kp];     al[1] = spl[r0 + 8][kp];
        al[2] = spl[r0][kp + 4]; al[3] = spl[r0 + 8][kp + 4];
        #pragma unroll
        for (int j = 0; j < 12; j++) {
            int nt = (j >> 2) * 16 + w * 4 + (j & 3);
            uint4 bvv = g_Bgi[(nt * 8 + k16) * 32 + l];
            mma16(acc[j], ah, bvv.x, bvv.y);
            mma16(acc[j], al, bvv.x, bvv.y);
            mma16(acc[j], ah, bvv.z, bvv.w);
        }
    }
    #pragma unroll
    for (int j = 0; j < 12; j++)
        #pragma unroll
        for (int x = 0; x < 4; x++) sgi[t][j * 4 + x] = acc[j][x];

    #pragma unroll
    for (int j = 0; j < 12; j++)
        #pragma unroll
        for (int x = 0; x < 4; x++) acc[j][x] = 0.f;
    #pragma unroll
    for (int k16 = 0; k16 < 8; k16++) {
        unsigned ah[4], al[4];
        int kp = k16 * 8 + c0;
        ah[0] = snh[r0][kp];     ah[1] = snh[r0 + 8][kp];
        ah[2] = snh[r0][kp + 4]; ah[3] = snh[r0 + 8][kp + 4];
        al[0] = snl[r0][kp];     al[1] = snl[r0 + 8][kp];
        al[2] = snl[r0][kp + 4]; al[3] = snl[r0 + 8][kp + 4];
        #pragma unroll
        for (int j = 0; j < 12; j++) {
            int nt = (j >> 2) * 16 + w * 4 + (j & 3);
            uint4 bvv = g_Bgh[(nt * 8 + k16) * 32 + l];
            mma16(acc[j], ah, bvv.x, bvv.y);
            mma16(acc[j], al, bvv.x, bvv.y);
            mma16(acc[j], ah, bvv.z, bvv.w);
        }
    }

    float G0 = g_G[base + r0], G1 = g_G[base + r0 + 8];
    #pragma unroll
    for (int j = 0; j < 4; j++) {
        int colg = w * 32 + j * 8 + 2 * c0;
        float2 o0, o1;
        #pragma unroll
        for (int b = 0; b < 2; b++) {
            int col = colg + b;
            float bfr = g_bf[col], bfz = g_bf[128 + col], bfn = g_bf[256 + col];
            float bir = bih[col], biz = bih[128 + col], bin = bih[256 + col];
            float bhr = bhh[col], bhz = bhh[128 + col], bhn = bhh[256 + col];
            {
                float gir = sgi[t][j * 4 + b]       + bir + G0 * bfr;
                float giz = sgi[t][(j + 4) * 4 + b] + biz + G0 * bfz;
                float gin = sgi[t][(j + 8) * 4 + b] + bin + G0 * bfn;
                float ghr = acc[j][b] + bhr, ghz = acc[j + 4][b] + bhz, ghn = acc[j + 8][b] + bhn;
                float rr = fsig(gir + ghr), zz = fsig(giz + ghz);
                float nv = ftanh(gin + rr * ghn);
                float xo = (1.f - zz) * nv + zz * snraw[r0][col];
                if (b) o0.y = xo; else o0.x = xo;
            }
            {
                float gir = sgi[t][j * 4 + b + 2]       + bir + G1 * bfr;
                float giz = sgi[t][(j + 4) * 4 + b + 2] + biz + G1 * bfz;
                float gin = sgi[t][(j + 8) * 4 + b + 2] + bin + G1 * bfn;
                float ghr = acc[j][b + 2] + bhr, ghz = acc[j + 4][b + 2] + bhz, ghn = acc[j + 8][b + 2] + bhn;
                float rr = fsig(gir + ghr), zz = fsig(giz + ghz);
                float nv = ftanh(gin + rr * ghn);
                float xo = (1.f - zz) * nv + zz * snraw[r0 + 8][col];
                if (b) o1.y = xo; else o1.x = xo;
            }
        }
        *(float2*)&out[(base + r0) * ND + colg]     = o0;
        *(float2*)&out[(base + r0 + 8) * ND + colg] = o1;
    }
}

extern "C" void kernel_launch(void* const* d_in, const int* in_sizes, int n_in,
                              void* d_out, int out_size) {
    const float* nf  = (const float*)d_in[0];
    const int*   ei  = (const int*)d_in[1];
    const float* ef  = (const float*)d_in[2];
    const float* W1  = (const float*)d_in[3];
    const float* b1  = (const float*)d_in[4];
    const float* lng = (const float*)d_in[5];
    const float* lnb = (const float*)d_in[6];
    const float* W2  = (const float*)d_in[7];
    const float* b2  = (const float*)d_in[8];
    const float* gw  = (const float*)d_in[9];
    const float* gb  = (const float*)d_in[10];
    const float* Wih = (const float*)d_in[11];
    const float* bih = (const float*)d_in[12];
    const float* Whh = (const float*)d_in[13];
    const float* bhh = (const float*)d_in[14];
    float* out = (float*)d_out;

    k_zero<<<(NN * ND / 4 + 255) / 256, 256>>>();
    k_transH<<<(384 * ND + 255) / 256, 256>>>(Whh);
    k_fold<<<ND, 384>>>(W2, Wih, b2);
    k_prep<<<136, 256>>>(W1);
    k_nodeAB_t<<<NN / 32, 128>>>(nf, b1);
    k_edge_t<<<1184, 128>>>(ef, ei, lng, lnb, gw, gb);
    k_gru_t<<<NN / 16, 128>>>(nf, bih, bhh, out);
}